// round 4
// baseline (speedup 1.0000x reference)
#include <cuda_runtime.h>

#define NN 50000
#define EE 800000
#define NBS 49   // ceil(NN/1024)

typedef unsigned long long u64;

// ---------------- scratch (device globals; no allocation allowed) ----------------
__device__ __align__(16) float g_h0[(size_t)NN * 128];   // layer input features
__device__ __align__(16) float g_h1[(size_t)NN * 128];   // h = x@W (interleaved [N][32][4])
__device__ __align__(16) float g_asrc[NN * 4];
__device__ __align__(16) float g_adst[NN * 4];
__device__ int g_deg[NN];
__device__ int g_ptr[NN + 1];
__device__ int g_bsum[64];
__device__ int g_csr[EE + NN];
__device__ int g_is64;

// ---------------- f32x2 helpers ----------------
__device__ __forceinline__ u64 pack2(float x) {
    u64 r;
    asm("mov.b64 %0, {%1, %1};" : "=l"(r) : "f"(x));
    return r;
}
__device__ __forceinline__ void ffma2(u64& d, u64 a, u64 b) {
    asm("fma.rn.f32x2 %0, %1, %2, %0;" : "+l"(d) : "l"(a), "l"(b));
}
__device__ __forceinline__ void unpack2(u64 v, float& lo, float& hi) {
    asm("mov.b64 {%0, %1}, %2;" : "=f"(lo), "=f"(hi) : "l"(v));
}

// ---------------- CSR build ----------------
__global__ void detect_kernel(const int* __restrict__ e32) {
    __shared__ int any;
    if (threadIdx.x == 0) any = 0;
    __syncthreads();
    int local = 0;
    for (int i = threadIdx.x; i < 4096; i += blockDim.x)
        if (e32[2 * i + 1] != 0) local = 1;
    if (local) any = 1;
    __syncthreads();
    if (threadIdx.x == 0) g_is64 = (any == 0) ? 1 : 0;
}

__global__ void init_deg_kernel() {
    int n = blockIdx.x * blockDim.x + threadIdx.x;
    if (n < NN) g_deg[n] = 1;   // self loop
}

__global__ void hist_kernel(const void* __restrict__ ei) {
    int e = blockIdx.x * blockDim.x + threadIdx.x;
    if (e >= EE) return;
    int d = g_is64 ? (int)((const long long*)ei)[EE + e]
                   : ((const int*)ei)[EE + e];
    atomicAdd(&g_deg[d], 1);
}

__global__ void scan_local_kernel() {
    __shared__ int wsum[32];
    int t = threadIdx.x;
    int i = blockIdx.x * 1024 + t;
    int v = (i < NN) ? g_deg[i] : 0;
    int x = v;
    #pragma unroll
    for (int off = 1; off < 32; off <<= 1) {
        int y = __shfl_up_sync(0xffffffffu, x, off);
        if ((t & 31) >= off) x += y;
    }
    if ((t & 31) == 31) wsum[t >> 5] = x;
    __syncthreads();
    if (t < 32) {
        int w = wsum[t];
        #pragma unroll
        for (int off = 1; off < 32; off <<= 1) {
            int y = __shfl_up_sync(0xffffffffu, w, off);
            if (t >= off) w += y;
        }
        wsum[t] = w;
    }
    __syncthreads();
    int incl = x + ((t >= 32) ? wsum[(t >> 5) - 1] : 0);
    if (i < NN) g_ptr[i] = incl - v;
    if (t == 1023) g_bsum[blockIdx.x] = incl;
}

__global__ void scan_block_kernel() {   // 1 warp
    int t = threadIdx.x;
    int carry = 0;
    for (int base = 0; base < NBS; base += 32) {
        int v = (base + t < NBS) ? g_bsum[base + t] : 0;
        int x = v;
        #pragma unroll
        for (int off = 1; off < 32; off <<= 1) {
            int y = __shfl_up_sync(0xffffffffu, x, off);
            if (t >= off) x += y;
        }
        if (base + t < NBS) g_bsum[base + t] = carry + x - v;
        carry += __shfl_sync(0xffffffffu, x, 31);
    }
    if (t == 0) g_ptr[NN] = carry;
}

// finalize ptr AND place self-loop + reset cursor (fused init_csr)
__global__ void scan_add_kernel() {
    int i = blockIdx.x * 1024 + threadIdx.x;
    if (i < NN) {
        int p = g_ptr[i] + g_bsum[blockIdx.x];
        g_ptr[i] = p;
        g_csr[p] = i;    // self loop at slot 0
        g_deg[i] = 1;    // scatter cursor
    }
}

__global__ void scatter_kernel(const void* __restrict__ ei) {
    int e = blockIdx.x * blockDim.x + threadIdx.x;
    if (e >= EE) return;
    int s, d;
    if (g_is64) {
        s = (int)((const long long*)ei)[e];
        d = (int)((const long long*)ei)[EE + e];
    } else {
        s = ((const int*)ei)[e];
        d = ((const int*)ei)[EE + e];
    }
    int pos = atomicAdd(&g_deg[d], 1);
    g_csr[g_ptr[d] + pos] = s;
}

// ---------------- big GEMM (M=128): transposed X tile, row-pair f32x2 accumulators ----------------
// H stored interleaved [N][32][4] (channel-major, heads packed).
__launch_bounds__(256)
__global__ void gemm128_kernel(const float* __restrict__ X, const float* __restrict__ W,
                               const float* __restrict__ att_s, const float* __restrict__ att_d,
                               float* __restrict__ H, float* __restrict__ asrc,
                               float* __restrict__ adst) {
    extern __shared__ float sh[];
    float* ws = sh;                 // [128][128]
    float* xs = sh + 128 * 128;     // transposed: [k=128][r=64]

    int t = threadIdx.x;
    int n0 = blockIdx.x * 64;

    for (int i = t; i < 128 * 32; i += 256)
        ((float4*)ws)[i] = ((const float4*)W)[i];
    for (int i = t; i < 64 * 32; i += 256) {
        int r = i & 63, c = i >> 6;          // coalesced smem writes (consecutive r)
        int n = n0 + r;
        float4 v = make_float4(0.f, 0.f, 0.f, 0.f);
        if (n < NN) v = ((const float4*)X)[(size_t)n * 32 + c];
        xs[(4 * c + 0) * 64 + r] = v.x;
        xs[(4 * c + 1) * 64 + r] = v.y;
        xs[(4 * c + 2) * 64 + r] = v.z;
        xs[(4 * c + 3) * 64 + r] = v.w;
    }
    __syncthreads();

    int cg = t & 31;          // column group (4 cols)
    int rg = t >> 5;          // row group (8 rows) — uniform per warp
    int j0 = 4 * cg;
    const float* xr = xs + rg * 8;

    u64 acc2[4][4];           // [row-pair][col]
    #pragma unroll
    for (int p = 0; p < 4; ++p)
        #pragma unroll
        for (int j = 0; j < 4; ++j) acc2[p][j] = 0ull;

    #pragma unroll 4
    for (int k = 0; k < 128; ++k) {
        float4 w4 = ((const float4*)ws)[k * 32 + cg];
        u64 wp0 = pack2(w4.x), wp1 = pack2(w4.y), wp2 = pack2(w4.z), wp3 = pack2(w4.w);
        const float* xk = xr + k * 64;
        #pragma unroll
        for (int p = 0; p < 4; ++p) {
            u64 xp = *(const u64*)(xk + 2 * p);   // rows 2p,2p+1 (warp-uniform broadcast)
            ffma2(acc2[p][0], xp, wp0);
            ffma2(acc2[p][1], xp, wp1);
            ffma2(acc2[p][2], xp, wp2);
            ffma2(acc2[p][3], xp, wp3);
        }
    }

    int h = cg >> 3;
    float4 as = ((const float4*)att_s)[cg];
    float4 ad = ((const float4*)att_d)[cg];

    #pragma unroll
    for (int p = 0; p < 4; ++p) {
        float a0, a1, b0, b1, c0, c1, d0, d1;
        unpack2(acc2[p][0], a0, a1);
        unpack2(acc2[p][1], b0, b1);
        unpack2(acc2[p][2], c0, c1);
        unpack2(acc2[p][3], d0, d1);
        float va[2][4] = {{a0, b0, c0, d0}, {a1, b1, c1, d1}};
        #pragma unroll
        for (int half = 0; half < 2; ++half) {
            int n = n0 + rg * 8 + 2 * p + half;
            float ps = va[half][0] * as.x + va[half][1] * as.y + va[half][2] * as.z + va[half][3] * as.w;
            float pd = va[half][0] * ad.x + va[half][1] * ad.y + va[half][2] * ad.z + va[half][3] * ad.w;
            #pragma unroll
            for (int off = 4; off >= 1; off >>= 1) {
                ps += __shfl_down_sync(0xffffffffu, ps, off, 8);
                pd += __shfl_down_sync(0xffffffffu, pd, off, 8);
            }
            if ((t & 7) == 0 && n < NN) {
                asrc[n * 4 + h] = ps;
                adst[n * 4 + h] = pd;
            }
            if (n < NN) {
                #pragma unroll
                for (int jj = 0; jj < 4; ++jj) {
                    int j = j0 + jj;
                    int pos = ((j & 31) << 2) | (j >> 5);   // [c][h]
                    H[(size_t)n * 128 + pos] = va[half][jj];
                }
            }
        }
    }
}

// ---------------- small GEMM (M=32, heads=1) ----------------
__launch_bounds__(256)
__global__ void gemm32_kernel(const float* __restrict__ X, const float* __restrict__ W,
                              const float* __restrict__ att_s, const float* __restrict__ att_d,
                              float* __restrict__ H, float* __restrict__ asrc,
                              float* __restrict__ adst) {
    constexpr int CG = 8;
    constexpr int RPT = 2;
    constexpr int XS = 132;
    extern __shared__ float sh[];
    float* ws = sh;                 // 128*32
    float* xs = sh + 128 * 32;      // 64*XS

    int t = threadIdx.x;
    int n0 = blockIdx.x * 64;

    for (int i = t; i < 128 * 32 / 4; i += 256)
        ((float4*)ws)[i] = ((const float4*)W)[i];
    for (int i = t; i < 64 * 32; i += 256) {
        int r = i >> 5, c = i & 31;
        int n = n0 + r;
        float4 v = make_float4(0.f, 0.f, 0.f, 0.f);
        if (n < NN) v = ((const float4*)X)[(size_t)n * 32 + c];
        *((float4*)(xs + r * XS + c * 4)) = v;
    }
    __syncthreads();

    int cg = t % CG;
    int rg = t / CG;

    u64 acc2[RPT][2];
    #pragma unroll
    for (int r = 0; r < RPT; ++r) { acc2[r][0] = 0ull; acc2[r][1] = 0ull; }

    const ulonglong2* wsp = (const ulonglong2*)ws;
    #pragma unroll 8
    for (int k = 0; k < 128; ++k) {
        ulonglong2 wp = wsp[k * CG + cg];
        #pragma unroll
        for (int r = 0; r < RPT; ++r) {
            u64 xp = pack2(xs[(rg * RPT + r) * XS + k]);
            ffma2(acc2[r][0], xp, wp.x);
            ffma2(acc2[r][1], xp, wp.y);
        }
    }

    float4 as = ((const float4*)att_s)[cg];
    float4 ad = ((const float4*)att_d)[cg];
    #pragma unroll
    for (int r = 0; r < RPT; ++r) {
        float acc[4];
        unpack2(acc2[r][0], acc[0], acc[1]);
        unpack2(acc2[r][1], acc[2], acc[3]);
        int n = n0 + rg * RPT + r;
        float ps = acc[0] * as.x + acc[1] * as.y + acc[2] * as.z + acc[3] * as.w;
        float pd = acc[0] * ad.x + acc[1] * ad.y + acc[2] * ad.z + acc[3] * ad.w;
        #pragma unroll
        for (int off = 4; off >= 1; off >>= 1) {
            ps += __shfl_down_sync(0xffffffffu, ps, off, 8);
            pd += __shfl_down_sync(0xffffffffu, pd, off, 8);
        }
        if ((t & 7) == 0 && n < NN) {
            asrc[n] = ps;
            adst[n] = pd;
        }
        if (n < NN)
            ((float4*)H)[(size_t)n * CG + cg] = make_float4(acc[0], acc[1], acc[2], acc[3]);
    }
}

// ---------------- per-node softmax + aggregation ----------------
__device__ __forceinline__ float lrelu(float v) { return fmaxf(v, 0.2f * v); }

template <int HEADS, int ACT>   // ACT: 0 = ELU, 1 = sigmoid
__launch_bounds__(256)
__global__ void agg_kernel(const float* __restrict__ feat,
                           const float* __restrict__ asrc, const float* __restrict__ adst,
                           const float* __restrict__ bias, float* __restrict__ out) {
    __shared__ float4 s_w4[8][32];
    __shared__ int s_src[8][32];
    int wid = threadIdx.x >> 5;
    int lane = threadIdx.x & 31;
    int n = blockIdx.x * 8 + wid;
    if (n >= NN) return;
    int beg = g_ptr[n], end = g_ptr[n + 1];
    const float4* feat4 = (const float4*)feat;

    if (HEADS == 4) {
        float4 ad = ((const float4*)adst)[n];
        float m0 = -1e30f, m1 = -1e30f, m2 = -1e30f, m3 = -1e30f;
        for (int e = beg + lane; e < end; e += 32) {
            int s = g_csr[e];
            float4 a = ((const float4*)asrc)[s];
            m0 = fmaxf(m0, lrelu(a.x + ad.x));
            m1 = fmaxf(m1, lrelu(a.y + ad.y));
            m2 = fmaxf(m2, lrelu(a.z + ad.z));
            m3 = fmaxf(m3, lrelu(a.w + ad.w));
        }
        #pragma unroll
        for (int off = 16; off >= 1; off >>= 1) {
            m0 = fmaxf(m0, __shfl_xor_sync(0xffffffffu, m0, off));
            m1 = fmaxf(m1, __shfl_xor_sync(0xffffffffu, m1, off));
            m2 = fmaxf(m2, __shfl_xor_sync(0xffffffffu, m2, off));
            m3 = fmaxf(m3, __shfl_xor_sync(0xffffffffu, m3, off));
        }
        float a0 = 0.f, a1 = 0.f, a2 = 0.f, a3 = 0.f;
        float s0 = 0.f, s1 = 0.f, s2 = 0.f, s3 = 0.f;
        for (int base = beg; base < end; base += 32) {
            int cnt = min(32, end - base);
            if (lane < cnt) {
                int s = g_csr[base + lane];
                float4 a = ((const float4*)asrc)[s];
                float4 wv;
                wv.x = __expf(lrelu(a.x + ad.x) - m0);
                wv.y = __expf(lrelu(a.y + ad.y) - m1);
                wv.z = __expf(lrelu(a.z + ad.z) - m2);
                wv.w = __expf(lrelu(a.w + ad.w) - m3);
                s_w4[wid][lane] = wv;
                s_src[wid][lane] = s;
                s0 += wv.x; s1 += wv.y; s2 += wv.z; s3 += wv.w;
            }
            __syncwarp();
            for (int i = 0; i < cnt; ++i) {
                float4 wv = s_w4[wid][i];
                int si = s_src[wid][i];
                float4 v = feat4[(size_t)si * 32 + lane];
                a0 += wv.x * v.x; a1 += wv.y * v.y; a2 += wv.z * v.z; a3 += wv.w * v.w;
            }
            __syncwarp();
        }
        #pragma unroll
        for (int off = 16; off >= 1; off >>= 1) {
            s0 += __shfl_xor_sync(0xffffffffu, s0, off);
            s1 += __shfl_xor_sync(0xffffffffu, s1, off);
            s2 += __shfl_xor_sync(0xffffffffu, s2, off);
            s3 += __shfl_xor_sync(0xffffffffu, s3, off);
        }
        float o0 = a0 / s0 + bias[lane];
        float o1 = a1 / s1 + bias[32 + lane];
        float o2 = a2 / s2 + bias[64 + lane];
        float o3 = a3 / s3 + bias[96 + lane];
        o0 = (o0 > 0.f) ? o0 : (__expf(o0) - 1.f);
        o1 = (o1 > 0.f) ? o1 : (__expf(o1) - 1.f);
        o2 = (o2 > 0.f) ? o2 : (__expf(o2) - 1.f);
        o3 = (o3 > 0.f) ? o3 : (__expf(o3) - 1.f);
        size_t b = (size_t)n * 128;
        out[b + lane] = o0;
        out[b + 32 + lane] = o1;
        out[b + 64 + lane] = o2;
        out[b + 96 + lane] = o3;
    } else {
        float* s_wf = (float*)&s_w4[wid][0];
        float ad = adst[n];
        float m = -1e30f;
        for (int e = beg + lane; e < end; e += 32)
            m = fmaxf(m, lrelu(asrc[g_csr[e]] + ad));
        #pragma unroll
        for (int off = 16; off >= 1; off >>= 1)
            m = fmaxf(m, __shfl_xor_sync(0xffffffffu, m, off));
        float acc = 0.f, ssum = 0.f;
        for (int base = beg; base < end; base += 32) {
            int cnt = min(32, end - base);
            if (lane < cnt) {
                int s = g_csr[base + lane];
                float wgt = __expf(lrelu(asrc[s] + ad) - m);
                s_wf[lane] = wgt;
                s_src[wid][lane] = s;
                ssum += wgt;
            }
            __syncwarp();
            for (int i = 0; i < cnt; ++i) {
                float wi = s_wf[i];
                int si = s_src[wid][i];
                acc += wi * feat[(size_t)si * 32 + lane];
            }
            __syncwarp();
        }
        #pragma unroll
        for (int off = 16; off >= 1; off >>= 1)
            ssum += __shfl_xor_sync(0xffffffffu, ssum, off);
        float o = acc / ssum + bias[lane];
        o = 1.f / (1.f + __expf(-o));
        out[(size_t)n * 32 + lane] = o;
    }
}

// ---------------- host launcher (single stream, capture-safe) ----------------
extern "C" void kernel_launch(void* const* d_in, const int* in_sizes, int n_in,
                              void* d_out, int out_size) {
    const float* x = (const float*)d_in[0];
    const void* ei = d_in[1];
    const float* W[4]  = {(const float*)d_in[2], (const float*)d_in[6],
                          (const float*)d_in[10], (const float*)d_in[14]};
    const float* As[4] = {(const float*)d_in[3], (const float*)d_in[7],
                          (const float*)d_in[11], (const float*)d_in[15]};
    const float* Ad[4] = {(const float*)d_in[4], (const float*)d_in[8],
                          (const float*)d_in[12], (const float*)d_in[16]};
    const float* B[4]  = {(const float*)d_in[5], (const float*)d_in[9],
                          (const float*)d_in[13], (const float*)d_in[17]};
    float* out = (float*)d_out;

    float *p_h0, *p_h1, *p_asrc, *p_adst;
    cudaGetSymbolAddress((void**)&p_h0, g_h0);
    cudaGetSymbolAddress((void**)&p_h1, g_h1);
    cudaGetSymbolAddress((void**)&p_asrc, g_asrc);
    cudaGetSymbolAddress((void**)&p_adst, g_adst);

    constexpr int SMEM_BIG = (128 * 128 + 128 * 64) * 4;   // 98304 B
    constexpr int SMEM_SMALL = (128 * 32 + 64 * 132) * 4;  // 50176 B
    cudaFuncSetAttribute(gemm128_kernel,
                         cudaFuncAttributeMaxDynamicSharedMemorySize, SMEM_BIG);
    cudaFuncSetAttribute(gemm32_kernel,
                         cudaFuncAttributeMaxDynamicSharedMemorySize, SMEM_SMALL);

    // CSR build
    detect_kernel<<<1, 256>>>((const int*)ei);
    init_deg_kernel<<<(NN + 255) / 256, 256>>>();
    hist_kernel<<<(EE + 255) / 256, 256>>>(ei);
    scan_local_kernel<<<NBS, 1024>>>();
    scan_block_kernel<<<1, 32>>>();
    scan_add_kernel<<<NBS, 1024>>>();   // also places self-loops + resets cursors
    scatter_kernel<<<(EE + 255) / 256, 256>>>(ei);

    const int GB = (NN + 63) / 64;   // 782
    const int AB = (NN + 7) / 8;     // 6250

    // layer 1
    gemm128_kernel<<<GB, 256, SMEM_BIG>>>(x, W[0], As[0], Ad[0], p_h1, p_asrc, p_adst);
    agg_kernel<4, 0><<<AB, 256>>>(p_h1, p_asrc, p_adst, B[0], p_h0);
    // layer 2
    gemm128_kernel<<<GB, 256, SMEM_BIG>>>(p_h0, W[1], As[1], Ad[1], p_h1, p_asrc, p_adst);
    agg_kernel<4, 0><<<AB, 256>>>(p_h1, p_asrc, p_adst, B[1], p_h0);
    // layer 3
    gemm128_kernel<<<GB, 256, SMEM_BIG>>>(p_h0, W[2], As[2], Ad[2], p_h1, p_asrc, p_adst);
    agg_kernel<4, 0><<<AB, 256>>>(p_h1, p_asrc, p_adst, B[2], p_h0);
    // layer 4 (heads=1, 32 labels) -> sigmoid -> d_out
    gemm32_kernel<<<GB, 256, SMEM_SMALL>>>(p_h0, W[3], As[3], Ad[3], p_h1, p_asrc, p_adst);
    agg_kernel<1, 1><<<AB, 256>>>(p_h1, p_asrc, p_adst, B[3], out);
}

// round 6
// speedup vs baseline: 1.0320x; 1.0320x over previous
#include <cuda_runtime.h>
#include <cstdint>

#define NN 50000
#define EE 800000
#define NBS 49   // ceil(NN/1024)

typedef unsigned long long u64;

// ---------------- scratch (device globals; no allocation allowed) ----------------
__device__ __align__(16) float g_h0[(size_t)NN * 128];   // layer input features
__device__ __align__(16) float g_h1[(size_t)NN * 128];   // h = x@W (interleaved [N][32][4])
__device__ __align__(16) float g_asrc[NN * 4];
__device__ __align__(16) float g_adst[NN * 4];
__device__ int g_deg[NN];
__device__ int g_ptr[NN + 1];
__device__ int g_bsum[64];
__device__ int g_csr[EE + NN];
__device__ int g_is64;

// ---------------- f32x2 helpers (scalar gemm32) ----------------
__device__ __forceinline__ u64 pack2(float x) {
    u64 r;
    asm("mov.b64 %0, {%1, %1};" : "=l"(r) : "f"(x));
    return r;
}
__device__ __forceinline__ void ffma2(u64& d, u64 a, u64 b) {
    asm("fma.rn.f32x2 %0, %1, %2, %0;" : "+l"(d) : "l"(a), "l"(b));
}
__device__ __forceinline__ void unpack2(u64 v, float& lo, float& hi) {
    asm("mov.b64 {%0, %1}, %2;" : "=f"(lo), "=f"(hi) : "l"(v));
}

// ---------------- tf32 helpers ----------------
__device__ __forceinline__ uint32_t f2tf(float x) {
    uint32_t u;
    asm("cvt.rna.tf32.f32 %0, %1;" : "=r"(u) : "f"(x));
    return u;
}
__device__ __forceinline__ void mma_tf32(float* c, const uint32_t* a, uint32_t b0, uint32_t b1) {
    asm volatile(
        "mma.sync.aligned.m16n8k8.row.col.f32.tf32.tf32.f32 "
        "{%0,%1,%2,%3}, {%4,%5,%6,%7}, {%8,%9}, {%0,%1,%2,%3};"
        : "+f"(c[0]), "+f"(c[1]), "+f"(c[2]), "+f"(c[3])
        : "r"(a[0]), "r"(a[1]), "r"(a[2]), "r"(a[3]), "r"(b0), "r"(b1));
}

// ---------------- CSR build ----------------
__global__ void detect_kernel(const int* __restrict__ e32) {
    __shared__ int any;
    if (threadIdx.x == 0) any = 0;
    __syncthreads();
    int local = 0;
    for (int i = threadIdx.x; i < 4096; i += blockDim.x)
        if (e32[2 * i + 1] != 0) local = 1;
    if (local) any = 1;
    __syncthreads();
    if (threadIdx.x == 0) g_is64 = (any == 0) ? 1 : 0;
}

__global__ void init_deg_kernel() {
    int n = blockIdx.x * blockDim.x + threadIdx.x;
    if (n < NN) g_deg[n] = 1;   // self loop
}

__global__ void hist_kernel(const void* __restrict__ ei) {
    int e = blockIdx.x * blockDim.x + threadIdx.x;
    if (e >= EE) return;
    int d = g_is64 ? (int)((const long long*)ei)[EE + e]
                   : ((const int*)ei)[EE + e];
    atomicAdd(&g_deg[d], 1);
}

__global__ void scan_local_kernel() {
    __shared__ int wsum[32];
    int t = threadIdx.x;
    int i = blockIdx.x * 1024 + t;
    int v = (i < NN) ? g_deg[i] : 0;
    int x = v;
    #pragma unroll
    for (int off = 1; off < 32; off <<= 1) {
        int y = __shfl_up_sync(0xffffffffu, x, off);
        if ((t & 31) >= off) x += y;
    }
    if ((t & 31) == 31) wsum[t >> 5] = x;
    __syncthreads();
    if (t < 32) {
        int w = wsum[t];
        #pragma unroll
        for (int off = 1; off < 32; off <<= 1) {
            int y = __shfl_up_sync(0xffffffffu, w, off);
            if (t >= off) w += y;
        }
        wsum[t] = w;
    }
    __syncthreads();
    int incl = x + ((t >= 32) ? wsum[(t >> 5) - 1] : 0);
    if (i < NN) g_ptr[i] = incl - v;
    if (t == 1023) g_bsum[blockIdx.x] = incl;
}

__global__ void scan_block_kernel() {   // 1 warp
    int t = threadIdx.x;
    int carry = 0;
    for (int base = 0; base < NBS; base += 32) {
        int v = (base + t < NBS) ? g_bsum[base + t] : 0;
        int x = v;
        #pragma unroll
        for (int off = 1; off < 32; off <<= 1) {
            int y = __shfl_up_sync(0xffffffffu, x, off);
            if (t >= off) x += y;
        }
        if (base + t < NBS) g_bsum[base + t] = carry + x - v;
        carry += __shfl_sync(0xffffffffu, x, 31);
    }
    if (t == 0) g_ptr[NN] = carry;
}

// finalize ptr AND place self-loop + reset cursor (fused init_csr)
__global__ void scan_add_kernel() {
    int i = blockIdx.x * 1024 + threadIdx.x;
    if (i < NN) {
        int p = g_ptr[i] + g_bsum[blockIdx.x];
        g_ptr[i] = p;
        g_csr[p] = i;    // self loop at slot 0
        g_deg[i] = 1;    // scatter cursor
    }
}

__global__ void scatter_kernel(const void* __restrict__ ei) {
    int e = blockIdx.x * blockDim.x + threadIdx.x;
    if (e >= EE) return;
    int s, d;
    if (g_is64) {
        s = (int)((const long long*)ei)[e];
        d = (int)((const long long*)ei)[EE + e];
    } else {
        s = ((const int*)ei)[e];
        d = ((const int*)ei)[EE + e];
    }
    int pos = atomicAdd(&g_deg[d], 1);
    g_csr[g_ptr[d] + pos] = s;
}

// ---------------- big GEMM via mma.sync tf32 (3xTF32 precision) ----------------
// Block: 256 threads, tile 128 rows x 128 cols, K=128 in two 64-halves.
// Warp (wm, wn) computes rows [wm*32, +32), cols [wn*64, +64).
// H stored interleaved [N][32][4]; asrc/adst computed in epilogue.
#define XP 68    // xs pitch (floats)
#define WP 136   // ws pitch (floats)
#define SP 132   // stage pitch (floats)

__global__ __launch_bounds__(256)
void gemm_tc_kernel(const float* __restrict__ X, const float* __restrict__ W,
                    const float* __restrict__ att_s, const float* __restrict__ att_d,
                    float* __restrict__ H, float* __restrict__ asrc,
                    float* __restrict__ adst) {
    extern __shared__ char sh[];
    float* att_ss = (float*)sh;                        // 128 f
    float* att_ds = (float*)(sh + 512);                // 128 f
    uint32_t* xs_hi = (uint32_t*)(sh + 1024);          // [128][XP]
    uint32_t* xs_lo = xs_hi + 128 * XP;
    uint32_t* ws_hi = xs_lo + 128 * XP;                // [64][WP]
    uint32_t* ws_lo = ws_hi + 64 * WP;
    float* stage = (float*)(sh + 1024);                // reused after mma

    int t = threadIdx.x;
    int lane = t & 31, wid = t >> 5;
    int g = lane >> 2, tig = lane & 3;
    int wm = wid >> 1, wn = wid & 1;
    int n0 = blockIdx.x * 128;

    if (t < 128) { att_ss[t] = att_s[t]; att_ds[t] = att_d[t]; }

    float acc[2][8][4];
    #pragma unroll
    for (int mt = 0; mt < 2; ++mt)
        #pragma unroll
        for (int nt = 0; nt < 8; ++nt)
            #pragma unroll
            for (int i = 0; i < 4; ++i) acc[mt][nt][i] = 0.f;

    for (int kh = 0; kh < 2; ++kh) {
        // load X[:, kh*64 .. +64) -> xs hi/lo
        #pragma unroll 2
        for (int idx = t; idx < 128 * 16; idx += 256) {
            int r = idx >> 4, c4 = idx & 15;
            int n = n0 + r;
            float4 v = make_float4(0.f, 0.f, 0.f, 0.f);
            if (n < NN) v = ((const float4*)X)[(size_t)n * 32 + kh * 16 + c4];
            float e[4] = {v.x, v.y, v.z, v.w};
            #pragma unroll
            for (int j = 0; j < 4; ++j) {
                uint32_t hu = f2tf(e[j]);
                float lo = e[j] - __uint_as_float(hu);
                xs_hi[r * XP + c4 * 4 + j] = hu;
                xs_lo[r * XP + c4 * 4 + j] = f2tf(lo);
            }
        }
        // load W[kh*64 .. +64, :] -> ws hi/lo  (row = k, col = n)
        #pragma unroll 2
        for (int idx = t; idx < 64 * 32; idx += 256) {
            int kr = idx >> 5, c4 = idx & 31;
            float4 v = ((const float4*)W)[(size_t)(kh * 64 + kr) * 32 + c4];
            float e[4] = {v.x, v.y, v.z, v.w};
            #pragma unroll
            for (int j = 0; j < 4; ++j) {
                uint32_t hu = f2tf(e[j]);
                float lo = e[j] - __uint_as_float(hu);
                ws_hi[kr * WP + c4 * 4 + j] = hu;
                ws_lo[kr * WP + c4 * 4 + j] = f2tf(lo);
            }
        }
        __syncthreads();

        const uint32_t* xa_h = xs_hi + (wm * 32 + g) * XP + tig;
        const uint32_t* xa_l = xs_lo + (wm * 32 + g) * XP + tig;
        const uint32_t* wb_h = ws_hi + tig * WP + wn * 64 + g;
        const uint32_t* wb_l = ws_lo + tig * WP + wn * 64 + g;

        #pragma unroll 4
        for (int ks = 0; ks < 8; ++ks) {
            uint32_t ah[2][4], al[2][4];
            #pragma unroll
            for (int mt = 0; mt < 2; ++mt) {
                int base = mt * 16 * XP + ks * 8;
                ah[mt][0] = xa_h[base];
                ah[mt][1] = xa_h[base + 8 * XP];
                ah[mt][2] = xa_h[base + 4];
                ah[mt][3] = xa_h[base + 8 * XP + 4];
                al[mt][0] = xa_l[base];
                al[mt][1] = xa_l[base + 8 * XP];
                al[mt][2] = xa_l[base + 4];
                al[mt][3] = xa_l[base + 8 * XP + 4];
            }
            #pragma unroll
            for (int nt = 0; nt < 8; ++nt) {
                int boff = ks * 8 * WP + nt * 8;
                uint32_t bh0 = wb_h[boff], bh1 = wb_h[boff + 4 * WP];
                uint32_t bl0 = wb_l[boff], bl1 = wb_l[boff + 4 * WP];
                #pragma unroll
                for (int mt = 0; mt < 2; ++mt) {
                    mma_tf32(acc[mt][nt], ah[mt], bh0, bh1);   // hi*hi
                    mma_tf32(acc[mt][nt], al[mt], bh0, bh1);   // lo*hi
                    mma_tf32(acc[mt][nt], ah[mt], bl0, bl1);   // hi*lo
                }
            }
        }
        __syncthreads();
    }

    // ---- epilogue: attention dots (warp covers heads wn*2, wn*2+1) ----
    #pragma unroll
    for (int mt = 0; mt < 2; ++mt) {
        #pragma unroll
        for (int rh = 0; rh < 2; ++rh) {
            int n = n0 + wm * 32 + mt * 16 + g + rh * 8;
            float ps0 = 0.f, pd0 = 0.f, ps1 = 0.f, pd1 = 0.f;
            #pragma unroll
            for (int nt = 0; nt < 8; ++nt) {
                #pragma unroll
                for (int ci = 0; ci < 2; ++ci) {
                    int col = wn * 64 + nt * 8 + 2 * tig + ci;
                    float a = acc[mt][nt][rh * 2 + ci];
                    float s = att_ss[col], d = att_ds[col];
                    if (nt < 4) { ps0 += a * s; pd0 += a * d; }
                    else        { ps1 += a * s; pd1 += a * d; }
                }
            }
            #pragma unroll
            for (int off = 1; off <= 2; off <<= 1) {
                ps0 += __shfl_xor_sync(0xffffffffu, ps0, off);
                pd0 += __shfl_xor_sync(0xffffffffu, pd0, off);
                ps1 += __shfl_xor_sync(0xffffffffu, ps1, off);
                pd1 += __shfl_xor_sync(0xffffffffu, pd1, off);
            }
            if (tig == 0 && n < NN) {
                asrc[n * 4 + wn * 2] = ps0;
                adst[n * 4 + wn * 2] = pd0;
                asrc[n * 4 + wn * 2 + 1] = ps1;
                adst[n * 4 + wn * 2 + 1] = pd1;
            }
        }
    }

    // ---- stage accs to smem, then interleaved H store ----
    #pragma unroll
    for (int mt = 0; mt < 2; ++mt) {
        int rbase = wm * 32 + mt * 16 + g;
        #pragma unroll
        for (int nt = 0; nt < 8; ++nt) {
            int col = wn * 64 + nt * 8 + 2 * tig;
            stage[rbase * SP + col] = acc[mt][nt][0];
            stage[rbase * SP + col + 1] = acc[mt][nt][1];
            stage[(rbase + 8) * SP + col] = acc[mt][nt][2];
            stage[(rbase + 8) * SP + col + 1] = acc[mt][nt][3];
        }
    }
    __syncthreads();
    #pragma unroll 4
    for (int idx = t; idx < 128 * 32; idx += 256) {
        int r = idx >> 5, fc = idx & 31;
        int n = n0 + r;
        if (n < NN) {
            const float* sr = stage + r * SP;
            ((float4*)H)[(size_t)n * 32 + fc] =
                make_float4(sr[fc], sr[32 + fc], sr[64 + fc], sr[96 + fc]);
        }
    }
}

// ---------------- small GEMM (M=32, heads=1, scalar f32x2) ----------------
__launch_bounds__(256)
__global__ void gemm32_kernel(const float* __restrict__ X, const float* __restrict__ W,
                              const float* __restrict__ att_s, const float* __restrict__ att_d,
                              float* __restrict__ H, float* __restrict__ asrc,
                              float* __restrict__ adst) {
    constexpr int CG = 8;
    constexpr int RPT = 2;
    constexpr int XS = 132;
    extern __shared__ float shf[];
    float* ws = shf;                 // 128*32
    float* xs = shf + 128 * 32;      // 64*XS

    int t = threadIdx.x;
    int n0 = blockIdx.x * 64;

    for (int i = t; i < 128 * 32 / 4; i += 256)
        ((float4*)ws)[i] = ((const float4*)W)[i];
    for (int i = t; i < 64 * 32; i += 256) {
        int r = i >> 5, c = i & 31;
        int n = n0 + r;
        float4 v = make_float4(0.f, 0.f, 0.f, 0.f);
        if (n < NN) v = ((const float4*)X)[(size_t)n * 32 + c];
        *((float4*)(xs + r * XS + c * 4)) = v;
    }
    __syncthreads();

    int cg = t % CG;
    int rg = t / CG;

    u64 acc2[RPT][2];
    #pragma unroll
    for (int r = 0; r < RPT; ++r) { acc2[r][0] = 0ull; acc2[r][1] = 0ull; }

    const ulonglong2* wsp = (const ulonglong2*)ws;
    #pragma unroll 8
    for (int k = 0; k < 128; ++k) {
        ulonglong2 wp = wsp[k * CG + cg];
        #pragma unroll
        for (int r = 0; r < RPT; ++r) {
            u64 xp = pack2(xs[(rg * RPT + r) * XS + k]);
            ffma2(acc2[r][0], xp, wp.x);
            ffma2(acc2[r][1], xp, wp.y);
        }
    }

    float4 as = ((const float4*)att_s)[cg];
    float4 ad = ((const float4*)att_d)[cg];
    #pragma unroll
    for (int r = 0; r < RPT; ++r) {
        float acc[4];
        unpack2(acc2[r][0], acc[0], acc[1]);
        unpack2(acc2[r][1], acc[2], acc[3]);
        int n = n0 + rg * RPT + r;
        float ps = acc[0] * as.x + acc[1] * as.y + acc[2] * as.z + acc[3] * as.w;
        float pd = acc[0] * ad.x + acc[1] * ad.y + acc[2] * ad.z + acc[3] * ad.w;
        #pragma unroll
        for (int off = 4; off >= 1; off >>= 1) {
            ps += __shfl_down_sync(0xffffffffu, ps, off, 8);
            pd += __shfl_down_sync(0xffffffffu, pd, off, 8);
        }
        if ((t & 7) == 0 && n < NN) {
            asrc[n] = ps;
            adst[n] = pd;
        }
        if (n < NN)
            ((float4*)H)[(size_t)n * CG + cg] = make_float4(acc[0], acc[1], acc[2], acc[3]);
    }
}

// ---------------- per-node softmax + aggregation ----------------
__device__ __forceinline__ float lrelu(float v) { return fmaxf(v, 0.2f * v); }

template <int HEADS, int ACT>   // ACT: 0 = ELU, 1 = sigmoid
__launch_bounds__(256)
__global__ void agg_kernel(const float* __restrict__ feat,
                           const float* __restrict__ asrc, const float* __restrict__ adst,
                           const float* __restrict__ bias, float* __restrict__ out) {
    __shared__ float4 s_w4[8][32];
    __shared__ int s_src[8][32];
    int wid = threadIdx.x >> 5;
    int lane = threadIdx.x & 31;
    int n = blockIdx.x * 8 + wid;
    if (n >= NN) return;
    int beg = g_ptr[n], end = g_ptr[n + 1];
    const float4* feat4 = (const float4*)feat;

    if (HEADS == 4) {
        float4 ad = ((const float4*)adst)[n];
        float m0 = -1e30f, m1 = -1e30f, m2 = -1e30f, m3 = -1e30f;
        for (int e = beg + lane; e < end; e += 32) {
            int s = g_csr[e];
            float4 a = ((const float4*)asrc)[s];
            m0 = fmaxf(m0, lrelu(a.x + ad.x));
            m1 = fmaxf(m1, lrelu(a.y + ad.y));
            m2 = fmaxf(m2, lrelu(a.z + ad.z));
            m3 = fmaxf(m3, lrelu(a.w + ad.w));
        }
        #pragma unroll
        for (int off = 16; off >= 1; off >>= 1) {
            m0 = fmaxf(m0, __shfl_xor_sync(0xffffffffu, m0, off));
            m1 = fmaxf(m1, __shfl_xor_sync(0xffffffffu, m1, off));
            m2 = fmaxf(m2, __shfl_xor_sync(0xffffffffu, m2, off));
            m3 = fmaxf(m3, __shfl_xor_sync(0xffffffffu, m3, off));
        }
        float a0 = 0.f, a1 = 0.f, a2 = 0.f, a3 = 0.f;
        float s0 = 0.f, s1 = 0.f, s2 = 0.f, s3 = 0.f;
        for (int base = beg; base < end; base += 32) {
            int cnt = min(32, end - base);
            if (lane < cnt) {
                int s = g_csr[base + lane];
                float4 a = ((const float4*)asrc)[s];
                float4 wv;
                wv.x = __expf(lrelu(a.x + ad.x) - m0);
                wv.y = __expf(lrelu(a.y + ad.y) - m1);
                wv.z = __expf(lrelu(a.z + ad.z) - m2);
                wv.w = __expf(lrelu(a.w + ad.w) - m3);
                s_w4[wid][lane] = wv;
                s_src[wid][lane] = s;
                s0 += wv.x; s1 += wv.y; s2 += wv.z; s3 += wv.w;
            }
            __syncwarp();
            for (int i = 0; i < cnt; ++i) {
                float4 wv = s_w4[wid][i];
                int si = s_src[wid][i];
                float4 v = feat4[(size_t)si * 32 + lane];
                a0 += wv.x * v.x; a1 += wv.y * v.y; a2 += wv.z * v.z; a3 += wv.w * v.w;
            }
            __syncwarp();
        }
        #pragma unroll
        for (int off = 16; off >= 1; off >>= 1) {
            s0 += __shfl_xor_sync(0xffffffffu, s0, off);
            s1 += __shfl_xor_sync(0xffffffffu, s1, off);
            s2 += __shfl_xor_sync(0xffffffffu, s2, off);
            s3 += __shfl_xor_sync(0xffffffffu, s3, off);
        }
        float o0 = a0 / s0 + bias[lane];
        float o1 = a1 / s1 + bias[32 + lane];
        float o2 = a2 / s2 + bias[64 + lane];
        float o3 = a3 / s3 + bias[96 + lane];
        o0 = (o0 > 0.f) ? o0 : (__expf(o0) - 1.f);
        o1 = (o1 > 0.f) ? o1 : (__expf(o1) - 1.f);
        o2 = (o2 > 0.f) ? o2 : (__expf(o2) - 1.f);
        o3 = (o3 > 0.f) ? o3 : (__expf(o3) - 1.f);
        size_t b = (size_t)n * 128;
        out[b + lane] = o0;
        out[b + 32 + lane] = o1;
        out[b + 64 + lane] = o2;
        out[b + 96 + lane] = o3;
    } else {
        float* s_wf = (float*)&s_w4[wid][0];
        float ad = adst[n];
        float m = -1e30f;
        for (int e = beg + lane; e < end; e += 32)
            m = fmaxf(m, lrelu(asrc[g_csr[e]] + ad));
        #pragma unroll
        for (int off = 16; off >= 1; off >>= 1)
            m = fmaxf(m, __shfl_xor_sync(0xffffffffu, m, off));
        float acc = 0.f, ssum = 0.f;
        for (int base = beg; base < end; base += 32) {
            int cnt = min(32, end - base);
            if (lane < cnt) {
                int s = g_csr[base + lane];
                float wgt = __expf(lrelu(asrc[s] + ad) - m);
                s_wf[lane] = wgt;
                s_src[wid][lane] = s;
                ssum += wgt;
            }
            __syncwarp();
            for (int i = 0; i < cnt; ++i) {
                float wi = s_wf[i];
                int si = s_src[wid][i];
                acc += wi * feat[(size_t)si * 32 + lane];
            }
            __syncwarp();
        }
        #pragma unroll
        for (int off = 16; off >= 1; off >>= 1)
            ssum += __shfl_xor_sync(0xffffffffu, ssum, off);
        float o = acc / ssum + bias[lane];
        o = 1.f / (1.f + __expf(-o));
        out[(size_t)n * 32 + lane] = o;
    }
}

// ---------------- host launcher (single stream, capture-safe) ----------------
extern "C" void kernel_launch(void* const* d_in, const int* in_sizes, int n_in,
                              void* d_out, int out_size) {
    const float* x = (const float*)d_in[0];
    const void* ei = d_in[1];
    const float* W[4]  = {(const float*)d_in[2], (const float*)d_in[6],
                          (const float*)d_in[10], (const float*)d_in[14]};
    const float* As[4] = {(const float*)d_in[3], (const float*)d_in[7],
                          (const float*)d_in[11], (const float*)d_in[15]};
    const float* Ad[4] = {(const float*)d_in[4], (const float*)d_in[8],
                          (const float*)d_in[12], (const float*)d_in[16]};
    const float* B[4]  = {(const float*)d_in[5], (const float*)d_in[9],
                          (const float*)d_in[13], (const float*)d_in[17]};
    float* out = (float*)d_out;

    float *p_h0, *p_h1, *p_asrc, *p_adst;
    cudaGetSymbolAddress((void**)&p_h0, g_h0);
    cudaGetSymbolAddress((void**)&p_h1, g_h1);
    cudaGetSymbolAddress((void**)&p_asrc, g_asrc);
    cudaGetSymbolAddress((void**)&p_adst, g_adst);

    constexpr int SMEM_TC = 1024 + (2 * 128 * XP + 2 * 64 * WP) * 4;   // 1024+139264 = 140288
    constexpr int SMEM_SMALL = (128 * 32 + 64 * 132) * 4;              // 50176 B
    cudaFuncSetAttribute(gemm_tc_kernel,
                         cudaFuncAttributeMaxDynamicSharedMemorySize, SMEM_TC);
    cudaFuncSetAttribute(gemm32_kernel,
                         cudaFuncAttributeMaxDynamicSharedMemorySize, SMEM_SMALL);

    // CSR build
    detect_kernel<<<1, 256>>>((const int*)ei);
    init_deg_kernel<<<(NN + 255) / 256, 256>>>();
    hist_kernel<<<(EE + 255) / 256, 256>>>(ei);
    scan_local_kernel<<<NBS, 1024>>>();
    scan_block_kernel<<<1, 32>>>();
    scan_add_kernel<<<NBS, 1024>>>();   // also places self-loops + resets cursors
    scatter_kernel<<<(EE + 255) / 256, 256>>>(ei);

    const int GTC = (NN + 127) / 128;  // 391
    const int GB = (NN + 63) / 64;     // 782
    const int AB = (NN + 7) / 8;       // 6250

    // layer 1
    gemm_tc_kernel<<<GTC, 256, SMEM_TC>>>(x, W[0], As[0], Ad[0], p_h1, p_asrc, p_adst);
    agg_kernel<4, 0><<<AB, 256>>>(p_h1, p_asrc, p_adst, B[0], p_h0);
    // layer 2
    gemm_tc_kernel<<<GTC, 256, SMEM_TC>>>(p_h0, W[1], As[1], Ad[1], p_h1, p_asrc, p_adst);
    agg_kernel<4, 0><<<AB, 256>>>(p_h1, p_asrc, p_adst, B[1], p_h0);
    // layer 3
    gemm_tc_kernel<<<GTC, 256, SMEM_TC>>>(p_h0, W[2], As[2], Ad[2], p_h1, p_asrc, p_adst);
    agg_kernel<4, 0><<<AB, 256>>>(p_h1, p_asrc, p_adst, B[2], p_h0);
    // layer 4 (heads=1, 32 labels) -> sigmoid -> d_out
    gemm32_kernel<<<GB, 256, SMEM_SMALL>>>(p_h0, W[3], As[3], Ad[3], p_h1, p_asrc, p_adst);
    agg_kernel<1, 1><<<AB, 256>>>(p_h1, p_asrc, p_adst, B[3], out);
}

// round 8
// speedup vs baseline: 1.1182x; 1.0836x over previous
#include <cuda_runtime.h>
#include <cstdint>

#define NN 50000
#define EE 800000
#define NBS 49   // ceil(NN/1024)

typedef unsigned long long u64;

// ---------------- scratch (device globals; no allocation allowed) ----------------
__device__ __align__(16) float g_h0[(size_t)NN * 128];   // layer input features
__device__ __align__(16) float g_h1[(size_t)NN * 128];   // h = x@W (interleaved [N][32][4])
__device__ __align__(16) float g_asrc[NN * 4];
__device__ __align__(16) float g_adst[NN * 4];
__device__ int g_deg[NN];
__device__ int g_ptr[NN + 1];
__device__ int g_bsum[64];
__device__ int g_csr[EE + NN];
__device__ int g_is64;

// ---------------- f32x2 helpers (scalar gemm32) ----------------
__device__ __forceinline__ u64 pack2(float x) {
    u64 r;
    asm("mov.b64 %0, {%1, %1};" : "=l"(r) : "f"(x));
    return r;
}
__device__ __forceinline__ void ffma2(u64& d, u64 a, u64 b) {
    asm("fma.rn.f32x2 %0, %1, %2, %0;" : "+l"(d) : "l"(a), "l"(b));
}
__device__ __forceinline__ void unpack2(u64 v, float& lo, float& hi) {
    asm("mov.b64 {%0, %1}, %2;" : "=f"(lo), "=f"(hi) : "l"(v));
}

// ---------------- tf32 helpers ----------------
__device__ __forceinline__ uint32_t f2tf(float x) {
    uint32_t u;
    asm("cvt.rna.tf32.f32 %0, %1;" : "=r"(u) : "f"(x));
    return u;
}
__device__ __forceinline__ void mma_tf32(float* c, const uint32_t* a, uint32_t b0, uint32_t b1) {
    asm volatile(
        "mma.sync.aligned.m16n8k8.row.col.f32.tf32.tf32.f32 "
        "{%0,%1,%2,%3}, {%4,%5,%6,%7}, {%8,%9}, {%0,%1,%2,%3};"
        : "+f"(c[0]), "+f"(c[1]), "+f"(c[2]), "+f"(c[3])
        : "r"(a[0]), "r"(a[1]), "r"(a[2]), "r"(a[3]), "r"(b0), "r"(b1));
}

// ---------------- CSR build ----------------
__global__ void detect_kernel(const int* __restrict__ e32) {
    __shared__ int any;
    if (threadIdx.x == 0) any = 0;
    __syncthreads();
    int local = 0;
    for (int i = threadIdx.x; i < 4096; i += blockDim.x)
        if (e32[2 * i + 1] != 0) local = 1;
    if (local) any = 1;
    __syncthreads();
    if (threadIdx.x == 0) g_is64 = (any == 0) ? 1 : 0;
}

__global__ void init_deg_kernel() {
    int n = blockIdx.x * blockDim.x + threadIdx.x;
    if (n < NN) g_deg[n] = 1;   // self loop
}

__global__ void hist_kernel(const void* __restrict__ ei) {
    int e = blockIdx.x * blockDim.x + threadIdx.x;
    if (e >= EE) return;
    int d = g_is64 ? (int)((const long long*)ei)[EE + e]
                   : ((const int*)ei)[EE + e];
    atomicAdd(&g_deg[d], 1);
}

__global__ void scan_local_kernel() {
    __shared__ int wsum[32];
    int t = threadIdx.x;
    int i = blockIdx.x * 1024 + t;
    int v = (i < NN) ? g_deg[i] : 0;
    int x = v;
    #pragma unroll
    for (int off = 1; off < 32; off <<= 1) {
        int y = __shfl_up_sync(0xffffffffu, x, off);
        if ((t & 31) >= off) x += y;
    }
    if ((t & 31) == 31) wsum[t >> 5] = x;
    __syncthreads();
    if (t < 32) {
        int w = wsum[t];
        #pragma unroll
        for (int off = 1; off < 32; off <<= 1) {
            int y = __shfl_up_sync(0xffffffffu, w, off);
            if (t >= off) w += y;
        }
        wsum[t] = w;
    }
    __syncthreads();
    int incl = x + ((t >= 32) ? wsum[(t >> 5) - 1] : 0);
    if (i < NN) g_ptr[i] = incl - v;
    if (t == 1023) g_bsum[blockIdx.x] = incl;
}

__global__ void scan_block_kernel() {   // 1 warp
    int t = threadIdx.x;
    int carry = 0;
    for (int base = 0; base < NBS; base += 32) {
        int v = (base + t < NBS) ? g_bsum[base + t] : 0;
        int x = v;
        #pragma unroll
        for (int off = 1; off < 32; off <<= 1) {
            int y = __shfl_up_sync(0xffffffffu, x, off);
            if (t >= off) x += y;
        }
        if (base + t < NBS) g_bsum[base + t] = carry + x - v;
        carry += __shfl_sync(0xffffffffu, x, 31);
    }
    if (t == 0) g_ptr[NN] = carry;
}

// finalize ptr AND place self-loop + reset cursor
__global__ void scan_add_kernel() {
    int i = blockIdx.x * 1024 + threadIdx.x;
    if (i < NN) {
        int p = g_ptr[i] + g_bsum[blockIdx.x];
        g_ptr[i] = p;
        g_csr[p] = i;    // self loop at slot 0
        g_deg[i] = 1;    // scatter cursor
    }
}

__global__ void scatter_kernel(const void* __restrict__ ei) {
    int e = blockIdx.x * blockDim.x + threadIdx.x;
    if (e >= EE) return;
    int s, d;
    if (g_is64) {
        s = (int)((const long long*)ei)[e];
        d = (int)((const long long*)ei)[EE + e];
    } else {
        s = ((const int*)ei)[e];
        d = ((const int*)ei)[EE + e];
    }
    int pos = atomicAdd(&g_deg[d], 1);
    g_csr[g_ptr[d] + pos] = s;
}

// ---------------- big GEMM via mma.sync tf32 (3xTF32), 512 threads ----------------
// Block tile 128x128, K=128 in two 64-halves. 16 warps: wm=wid>>2 (32 rows), wn=wid&3 (32 cols = head wn).
#define XP 68    // xs pitch (floats)
#define WP 136   // ws pitch (floats)
#define SP 132   // stage pitch (floats)

__global__ __launch_bounds__(512)
void gemm_tc_kernel(const float* __restrict__ X, const float* __restrict__ W,
                    const float* __restrict__ att_s, const float* __restrict__ att_d,
                    float* __restrict__ H, float* __restrict__ asrc,
                    float* __restrict__ adst) {
    extern __shared__ char sh[];
    float* att_ss = (float*)sh;                        // 128 f
    float* att_ds = (float*)(sh + 512);                // 128 f
    uint32_t* xs_hi = (uint32_t*)(sh + 1024);          // [128][XP]
    uint32_t* xs_lo = xs_hi + 128 * XP;
    uint32_t* ws_hi = xs_lo + 128 * XP;                // [64][WP]
    uint32_t* ws_lo = ws_hi + 64 * WP;
    float* stage = (float*)(sh + 1024);                // reused after mma

    int t = threadIdx.x;
    int lane = t & 31, wid = t >> 5;
    int g = lane >> 2, tig = lane & 3;
    int wm = wid >> 2, wn = wid & 3;
    int n0 = blockIdx.x * 128;

    if (t < 128) { att_ss[t] = att_s[t]; att_ds[t] = att_d[t]; }

    float acc[2][4][4];   // [mt 16-row][nt 8-col][frag]
    #pragma unroll
    for (int mt = 0; mt < 2; ++mt)
        #pragma unroll
        for (int nt = 0; nt < 4; ++nt)
            #pragma unroll
            for (int i = 0; i < 4; ++i) acc[mt][nt][i] = 0.f;

    for (int kh = 0; kh < 2; ++kh) {
        #pragma unroll 2
        for (int idx = t; idx < 128 * 16; idx += 512) {
            int r = idx >> 4, c4 = idx & 15;
            int n = n0 + r;
            float4 v = make_float4(0.f, 0.f, 0.f, 0.f);
            if (n < NN) v = ((const float4*)X)[(size_t)n * 32 + kh * 16 + c4];
            float e[4] = {v.x, v.y, v.z, v.w};
            #pragma unroll
            for (int j = 0; j < 4; ++j) {
                uint32_t hu = f2tf(e[j]);
                float lo = e[j] - __uint_as_float(hu);
                xs_hi[r * XP + c4 * 4 + j] = hu;
                xs_lo[r * XP + c4 * 4 + j] = f2tf(lo);
            }
        }
        #pragma unroll 2
        for (int idx = t; idx < 64 * 32; idx += 512) {
            int kr = idx >> 5, c4 = idx & 31;
            float4 v = ((const float4*)W)[(size_t)(kh * 64 + kr) * 32 + c4];
            float e[4] = {v.x, v.y, v.z, v.w};
            #pragma unroll
            for (int j = 0; j < 4; ++j) {
                uint32_t hu = f2tf(e[j]);
                float lo = e[j] - __uint_as_float(hu);
                ws_hi[kr * WP + c4 * 4 + j] = hu;
                ws_lo[kr * WP + c4 * 4 + j] = f2tf(lo);
            }
        }
        __syncthreads();

        const uint32_t* xa_h = xs_hi + (wm * 32 + g) * XP + tig;
        const uint32_t* xa_l = xs_lo + (wm * 32 + g) * XP + tig;
        const uint32_t* wb_h = ws_hi + tig * WP + wn * 32 + g;
        const uint32_t* wb_l = ws_lo + tig * WP + wn * 32 + g;

        #pragma unroll 4
        for (int ks = 0; ks < 8; ++ks) {
            uint32_t ah[2][4], al[2][4];
            #pragma unroll
            for (int mt = 0; mt < 2; ++mt) {
                int base = mt * 16 * XP + ks * 8;
                ah[mt][0] = xa_h[base];
                ah[mt][1] = xa_h[base + 8 * XP];
                ah[mt][2] = xa_h[base + 4];
                ah[mt][3] = xa_h[base + 8 * XP + 4];
                al[mt][0] = xa_l[base];
                al[mt][1] = xa_l[base + 8 * XP];
                al[mt][2] = xa_l[base + 4];
                al[mt][3] = xa_l[base + 8 * XP + 4];
            }
            #pragma unroll
            for (int nt = 0; nt < 4; ++nt) {
                int boff = ks * 8 * WP + nt * 8;
                uint32_t bh0 = wb_h[boff], bh1 = wb_h[boff + 4 * WP];
                uint32_t bl0 = wb_l[boff], bl1 = wb_l[boff + 4 * WP];
                #pragma unroll
                for (int mt = 0; mt < 2; ++mt) {
                    mma_tf32(acc[mt][nt], ah[mt], bh0, bh1);   // hi*hi
                    mma_tf32(acc[mt][nt], al[mt], bh0, bh1);   // lo*hi
                    mma_tf32(acc[mt][nt], ah[mt], bl0, bl1);   // hi*lo
                }
            }
        }
        __syncthreads();
    }

    // ---- epilogue: attention dots (warp covers exactly head wn) ----
    #pragma unroll
    for (int mt = 0; mt < 2; ++mt) {
        #pragma unroll
        for (int rh = 0; rh < 2; ++rh) {
            int n = n0 + wm * 32 + mt * 16 + g + rh * 8;
            float ps = 0.f, pd = 0.f;
            #pragma unroll
            for (int nt = 0; nt < 4; ++nt) {
                #pragma unroll
                for (int ci = 0; ci < 2; ++ci) {
                    int col = wn * 32 + nt * 8 + 2 * tig + ci;
                    float a = acc[mt][nt][rh * 2 + ci];
                    ps += a * att_ss[col];
                    pd += a * att_ds[col];
                }
            }
            #pragma unroll
            for (int off = 1; off <= 2; off <<= 1) {
                ps += __shfl_xor_sync(0xffffffffu, ps, off);
                pd += __shfl_xor_sync(0xffffffffu, pd, off);
            }
            if (tig == 0 && n < NN) {
                asrc[n * 4 + wn] = ps;
                adst[n * 4 + wn] = pd;
            }
        }
    }

    // ---- stage accs to smem, then interleaved H store ----
    #pragma unroll
    for (int mt = 0; mt < 2; ++mt) {
        int rbase = wm * 32 + mt * 16 + g;
        #pragma unroll
        for (int nt = 0; nt < 4; ++nt) {
            int col = wn * 32 + nt * 8 + 2 * tig;
            stage[rbase * SP + col] = acc[mt][nt][0];
            stage[rbase * SP + col + 1] = acc[mt][nt][1];
            stage[(rbase + 8) * SP + col] = acc[mt][nt][2];
            stage[(rbase + 8) * SP + col + 1] = acc[mt][nt][3];
        }
    }
    __syncthreads();
    #pragma unroll 2
    for (int idx = t; idx < 128 * 32; idx += 512) {
        int r = idx >> 5, fc = idx & 31;
        int n = n0 + r;
        if (n < NN) {
            const float* sr = stage + r * SP;
            ((float4*)H)[(size_t)n * 32 + fc] =
                make_float4(sr[fc], sr[32 + fc], sr[64 + fc], sr[96 + fc]);
        }
    }
}

// ---------------- small GEMM (M=32, heads=1, scalar f32x2) ----------------
__launch_bounds__(256)
__global__ void gemm32_kernel(const float* __restrict__ X, const float* __restrict__ W,
                              const float* __restrict__ att_s, const float* __restrict__ att_d,
                              float* __restrict__ H, float* __restrict__ asrc,
                              float* __restrict__ adst) {
    constexpr int CG = 8;
    constexpr int RPT = 2;
    constexpr int XS = 132;
    extern __shared__ float shf[];
    float* ws = shf;                 // 128*32
    float* xs = shf + 128 * 32;      // 64*XS

    int t = threadIdx.x;
    int n0 = blockIdx.x * 64;

    for (int i = t; i < 128 * 32 / 4; i += 256)
        ((float4*)ws)[i] = ((const float4*)W)[i];
    for (int i = t; i < 64 * 32; i += 256) {
        int r = i >> 5, c = i & 31;
        int n = n0 + r;
        float4 v = make_float4(0.f, 0.f, 0.f, 0.f);
        if (n < NN) v = ((const float4*)X)[(size_t)n * 32 + c];
        *((float4*)(xs + r * XS + c * 4)) = v;
    }
    __syncthreads();

    int cg = t % CG;
    int rg = t / CG;

    u64 acc2[RPT][2];
    #pragma unroll
    for (int r = 0; r < RPT; ++r) { acc2[r][0] = 0ull; acc2[r][1] = 0ull; }

    const ulonglong2* wsp = (const ulonglong2*)ws;
    #pragma unroll 8
    for (int k = 0; k < 128; ++k) {
        ulonglong2 wp = wsp[k * CG + cg];
        #pragma unroll
        for (int r = 0; r < RPT; ++r) {
            u64 xp = pack2(xs[(rg * RPT + r) * XS + k]);
            ffma2(acc2[r][0], xp, wp.x);
            ffma2(acc2[r][1], xp, wp.y);
        }
    }

    float4 as = ((const float4*)att_s)[cg];
    float4 ad = ((const float4*)att_d)[cg];
    #pragma unroll
    for (int r = 0; r < RPT; ++r) {
        float acc[4];
        unpack2(acc2[r][0], acc[0], acc[1]);
        unpack2(acc2[r][1], acc[2], acc[3]);
        int n = n0 + rg * RPT + r;
        float ps = acc[0] * as.x + acc[1] * as.y + acc[2] * as.z + acc[3] * as.w;
        float pd = acc[0] * ad.x + acc[1] * ad.y + acc[2] * ad.z + acc[3] * ad.w;
        #pragma unroll
        for (int off = 4; off >= 1; off >>= 1) {
            ps += __shfl_down_sync(0xffffffffu, ps, off, 8);
            pd += __shfl_down_sync(0xffffffffu, pd, off, 8);
        }
        if ((t & 7) == 0 && n < NN) {
            asrc[n] = ps;
            adst[n] = pd;
        }
        if (n < NN)
            ((float4*)H)[(size_t)n * CG + cg] = make_float4(acc[0], acc[1], acc[2], acc[3]);
    }
}

// ---------------- per-node ONLINE softmax + aggregation (single edge pass) ----------------
__device__ __forceinline__ float lrelu(float v) { return fmaxf(v, 0.2f * v); }

template <int HEADS, int ACT>   // ACT: 0 = ELU, 1 = sigmoid
__launch_bounds__(256)
__global__ void agg_kernel(const float* __restrict__ feat,
                           const float* __restrict__ asrc, const float* __restrict__ adst,
                           const float* __restrict__ bias, float* __restrict__ out) {
    __shared__ float4 s_w4[8][32];
    __shared__ int s_src[8][32];
    int wid = threadIdx.x >> 5;
    int lane = threadIdx.x & 31;
    int n = blockIdx.x * 8 + wid;
    if (n >= NN) return;
    int beg = g_ptr[n], end = g_ptr[n + 1];
    const float4* feat4 = (const float4*)feat;

    if (HEADS == 4) {
        float4 ad = ((const float4*)adst)[n];
        float m0 = -1e30f, m1 = -1e30f, m2 = -1e30f, m3 = -1e30f;
        float a0 = 0.f, a1 = 0.f, a2 = 0.f, a3 = 0.f;
        float s0 = 0.f, s1 = 0.f, s2 = 0.f, s3 = 0.f;
        for (int base = beg; base < end; base += 32) {
            int cnt = min(32, end - base);
            float l0 = -1e30f, l1 = -1e30f, l2 = -1e30f, l3 = -1e30f;
            int src = 0;
            if (lane < cnt) {
                src = g_csr[base + lane];
                float4 a = ((const float4*)asrc)[src];
                l0 = lrelu(a.x + ad.x);
                l1 = lrelu(a.y + ad.y);
                l2 = lrelu(a.z + ad.z);
                l3 = lrelu(a.w + ad.w);
            }
            // chunk max (warp-wide; invalid lanes = -1e30)
            float c0 = l0, c1 = l1, c2 = l2, c3 = l3;
            #pragma unroll
            for (int off = 16; off >= 1; off >>= 1) {
                c0 = fmaxf(c0, __shfl_xor_sync(0xffffffffu, c0, off));
                c1 = fmaxf(c1, __shfl_xor_sync(0xffffffffu, c1, off));
                c2 = fmaxf(c2, __shfl_xor_sync(0xffffffffu, c2, off));
                c3 = fmaxf(c3, __shfl_xor_sync(0xffffffffu, c3, off));
            }
            float nm0 = fmaxf(m0, c0), nm1 = fmaxf(m1, c1);
            float nm2 = fmaxf(m2, c2), nm3 = fmaxf(m3, c3);
            float f0 = __expf(m0 - nm0), f1 = __expf(m1 - nm1);
            float f2 = __expf(m2 - nm2), f3 = __expf(m3 - nm3);
            a0 *= f0; a1 *= f1; a2 *= f2; a3 *= f3;
            s0 *= f0; s1 *= f1; s2 *= f2; s3 *= f3;
            m0 = nm0; m1 = nm1; m2 = nm2; m3 = nm3;
            if (lane < cnt) {
                float4 wv;
                wv.x = __expf(l0 - m0);
                wv.y = __expf(l1 - m1);
                wv.z = __expf(l2 - m2);
                wv.w = __expf(l3 - m3);
                s_w4[wid][lane] = wv;
                s_src[wid][lane] = src;
            }
            __syncwarp();
            for (int i = 0; i < cnt; ++i) {
                float4 wv = s_w4[wid][i];
                int si = s_src[wid][i];
                float4 v = feat4[(size_t)si * 32 + lane];
                a0 += wv.x * v.x; a1 += wv.y * v.y; a2 += wv.z * v.z; a3 += wv.w * v.w;
                s0 += wv.x; s1 += wv.y; s2 += wv.z; s3 += wv.w;
            }
            __syncwarp();
        }
        // s* are warp-uniform (accumulated in the broadcast loop) — no reduce needed
        float o0 = a0 / s0 + bias[lane];
        float o1 = a1 / s1 + bias[32 + lane];
        float o2 = a2 / s2 + bias[64 + lane];
        float o3 = a3 / s3 + bias[96 + lane];
        o0 = (o0 > 0.f) ? o0 : (__expf(o0) - 1.f);
        o1 = (o1 > 0.f) ? o1 : (__expf(o1) - 1.f);
        o2 = (o2 > 0.f) ? o2 : (__expf(o2) - 1.f);
        o3 = (o3 > 0.f) ? o3 : (__expf(o3) - 1.f);
        size_t b = (size_t)n * 128;
        out[b + lane] = o0;
        out[b + 32 + lane] = o1;
        out[b + 64 + lane] = o2;
        out[b + 96 + lane] = o3;
    } else {
        float* s_wf = (float*)&s_w4[wid][0];
        float ad = adst[n];
        float m = -1e30f, acc = 0.f, ssum = 0.f;
        for (int base = beg; base < end; base += 32) {
            int cnt = min(32, end - base);
            float l = -1e30f;
            int src = 0;
            if (lane < cnt) {
                src = g_csr[base + lane];
                l = lrelu(asrc[src] + ad);
            }
            float c = l;
            #pragma unroll
            for (int off = 16; off >= 1; off >>= 1)
                c = fmaxf(c, __shfl_xor_sync(0xffffffffu, c, off));
            float nm = fmaxf(m, c);
            float f = __expf(m - nm);
            acc *= f; ssum *= f;
            m = nm;
            if (lane < cnt) {
                s_wf[lane] = __expf(l - m);
                s_src[wid][lane] = src;
            }
            __syncwarp();
            for (int i = 0; i < cnt; ++i) {
                float wi = s_wf[i];
                int si = s_src[wid][i];
                acc += wi * feat[(size_t)si * 32 + lane];
                ssum += wi;
            }
            __syncwarp();
        }
        float o = acc / ssum + bias[lane];
        o = 1.f / (1.f + __expf(-o));
        out[(size_t)n * 32 + lane] = o;
    }
}

// ---------------- host launcher (single stream, capture-safe) ----------------
extern "C" void kernel_launch(void* const* d_in, const int* in_sizes, int n_in,
                              void* d_out, int out_size) {
    const float* x = (const float*)d_in[0];
    const void* ei = d_in[1];
    const float* W[4]  = {(const float*)d_in[2], (const float*)d_in[6],
                          (const float*)d_in[10], (const float*)d_in[14]};
    const float* As[4] = {(const float*)d_in[3], (const float*)d_in[7],
                          (const float*)d_in[11], (const float*)d_in[15]};
    const float* Ad[4] = {(const float*)d_in[4], (const float*)d_in[8],
                          (const float*)d_in[12], (const float*)d_in[16]};
    const float* B[4]  = {(const float*)d_in[5], (const float*)d_in[9],
                          (const float*)d_in[13], (const float*)d_in[17]};
    float* out = (float*)d_out;

    float *p_h0, *p_h1, *p_asrc, *p_adst;
    cudaGetSymbolAddress((void**)&p_h0, g_h0);
    cudaGetSymbolAddress((void**)&p_h1, g_h1);
    cudaGetSymbolAddress((void**)&p_asrc, g_asrc);
    cudaGetSymbolAddress((void**)&p_adst, g_adst);

    constexpr int SMEM_TC = 1024 + (2 * 128 * XP + 2 * 64 * WP) * 4;   // 140288
    constexpr int SMEM_SMALL = (128 * 32 + 64 * 132) * 4;              // 50176 B
    cudaFuncSetAttribute(gemm_tc_kernel,
                         cudaFuncAttributeMaxDynamicSharedMemorySize, SMEM_TC);
    cudaFuncSetAttribute(gemm32_kernel,
                         cudaFuncAttributeMaxDynamicSharedMemorySize, SMEM_SMALL);

    const int GTC = (NN + 127) / 128;  // 391
    const int GB = (NN + 63) / 64;     // 782
    const int AB = (NN + 7) / 8;       // 6250

    // CSR build, with layer-1 GEMM (CSR-independent) slotted at launch index 3
    // so the ncu capture lands on it.
    detect_kernel<<<1, 256>>>((const int*)ei);                             // 0
    init_deg_kernel<<<(NN + 255) / 256, 256>>>();                          // 1
    hist_kernel<<<(EE + 255) / 256, 256>>>(ei);                            // 2
    gemm_tc_kernel<<<GTC, 512, SMEM_TC>>>(x, W[0], As[0], Ad[0],           // 3 (profiled)
                                          p_h1, p_asrc, p_adst);
    scan_local_kernel<<<NBS, 1024>>>();                                    // 4
    scan_block_kernel<<<1, 32>>>();                                        // 5
    scan_add_kernel<<<NBS, 1024>>>();                                      // 6
    scatter_kernel<<<(EE + 255) / 256, 256>>>(ei);                         // 7

    // layer 1 aggregation
    agg_kernel<4, 0><<<AB, 256>>>(p_h1, p_asrc, p_adst, B[0], p_h0);
    // layer 2
    gemm_tc_kernel<<<GTC, 512, SMEM_TC>>>(p_h0, W[1], As[1], Ad[1], p_h1, p_asrc, p_adst);
    agg_kernel<4, 0><<<AB, 256>>>(p_h1, p_asrc, p_adst, B[1], p_h0);
    // layer 3
    gemm_tc_kernel<<<GTC, 512, SMEM_TC>>>(p_h0, W[2], As[2], Ad[2], p_h1, p_asrc, p_adst);
    agg_kernel<4, 0><<<AB, 256>>>(p_h1, p_asrc, p_adst, B[2], p_h0);
    // layer 4 (heads=1, 32 labels) -> sigmoid -> d_out
    gemm32_kernel<<<GB, 256, SMEM_SMALL>>>(p_h0, W[3], As[3], Ad[3], p_h1, p_asrc, p_adst);
    agg_kernel<1, 1><<<AB, 256>>>(p_h1, p_asrc, p_adst, B[3], out);
}

// round 9
// speedup vs baseline: 1.1474x; 1.0261x over previous
#include <cuda_runtime.h>
#include <cstdint>

#define NN 50000
#define EE 800000
#define NBS 49   // ceil(NN/1024)

typedef unsigned long long u64;

// ---------------- scratch (device globals; no allocation allowed) ----------------
__device__ __align__(16) float g_h0[(size_t)NN * 128];   // layer input features
__device__ __align__(16) float g_h1[(size_t)NN * 128];   // h = x@W (interleaved [N][32][4])
__device__ __align__(16) float g_asrc[NN * 4];
__device__ __align__(16) float g_adst[NN * 4];
__device__ int g_deg[NN];
__device__ int g_ptr[NN + 1];
__device__ int g_bsum[64];
__device__ int g_csr[EE + NN];
__device__ int g_is64;

// ---------------- f32x2 helpers (scalar gemm32) ----------------
__device__ __forceinline__ u64 pack2(float x) {
    u64 r;
    asm("mov.b64 %0, {%1, %1};" : "=l"(r) : "f"(x));
    return r;
}
__device__ __forceinline__ void ffma2(u64& d, u64 a, u64 b) {
    asm("fma.rn.f32x2 %0, %1, %2, %0;" : "+l"(d) : "l"(a), "l"(b));
}
__device__ __forceinline__ void unpack2(u64 v, float& lo, float& hi) {
    asm("mov.b64 {%0, %1}, %2;" : "=f"(lo), "=f"(hi) : "l"(v));
}

// ---------------- tf32 helpers ----------------
__device__ __forceinline__ uint32_t f2tf(float x) {
    uint32_t u;
    asm("cvt.rna.tf32.f32 %0, %1;" : "=r"(u) : "f"(x));
    return u;
}
__device__ __forceinline__ void mma_tf32(float* c, const uint32_t* a, uint32_t b0, uint32_t b1) {
    asm volatile(
        "mma.sync.aligned.m16n8k8.row.col.f32.tf32.tf32.f32 "
        "{%0,%1,%2,%3}, {%4,%5,%6,%7}, {%8,%9}, {%0,%1,%2,%3};"
        : "+f"(c[0]), "+f"(c[1]), "+f"(c[2]), "+f"(c[3])
        : "r"(a[0]), "r"(a[1]), "r"(a[2]), "r"(a[3]), "r"(b0), "r"(b1));
}

// ---------------- CSR build ----------------
__global__ void detect_kernel(const int* __restrict__ e32) {
    __shared__ int any;
    if (threadIdx.x == 0) any = 0;
    __syncthreads();
    int local = 0;
    for (int i = threadIdx.x; i < 4096; i += blockDim.x)
        if (e32[2 * i + 1] != 0) local = 1;
    if (local) any = 1;
    __syncthreads();
    if (threadIdx.x == 0) g_is64 = (any == 0) ? 1 : 0;
}

__global__ void init_deg_kernel() {
    int n = blockIdx.x * blockDim.x + threadIdx.x;
    if (n < NN) g_deg[n] = 1;   // self loop
}

__global__ void hist_kernel(const void* __restrict__ ei) {
    int e = blockIdx.x * blockDim.x + threadIdx.x;
    if (e >= EE) return;
    int d = g_is64 ? (int)((const long long*)ei)[EE + e]
                   : ((const int*)ei)[EE + e];
    atomicAdd(&g_deg[d], 1);
}

__global__ void scan_local_kernel() {
    __shared__ int wsum[32];
    int t = threadIdx.x;
    int i = blockIdx.x * 1024 + t;
    int v = (i < NN) ? g_deg[i] : 0;
    int x = v;
    #pragma unroll
    for (int off = 1; off < 32; off <<= 1) {
        int y = __shfl_up_sync(0xffffffffu, x, off);
        if ((t & 31) >= off) x += y;
    }
    if ((t & 31) == 31) wsum[t >> 5] = x;
    __syncthreads();
    if (t < 32) {
        int w = wsum[t];
        #pragma unroll
        for (int off = 1; off < 32; off <<= 1) {
            int y = __shfl_up_sync(0xffffffffu, w, off);
            if (t >= off) w += y;
        }
        wsum[t] = w;
    }
    __syncthreads();
    int incl = x + ((t >= 32) ? wsum[(t >> 5) - 1] : 0);
    if (i < NN) g_ptr[i] = incl - v;
    if (t == 1023) g_bsum[blockIdx.x] = incl;
}

__global__ void scan_block_kernel() {   // 1 warp
    int t = threadIdx.x;
    int carry = 0;
    for (int base = 0; base < NBS; base += 32) {
        int v = (base + t < NBS) ? g_bsum[base + t] : 0;
        int x = v;
        #pragma unroll
        for (int off = 1; off < 32; off <<= 1) {
            int y = __shfl_up_sync(0xffffffffu, x, off);
            if (t >= off) x += y;
        }
        if (base + t < NBS) g_bsum[base + t] = carry + x - v;
        carry += __shfl_sync(0xffffffffu, x, 31);
    }
    if (t == 0) g_ptr[NN] = carry;
}

// finalize ptr AND place self-loop + reset cursor
__global__ void scan_add_kernel() {
    int i = blockIdx.x * 1024 + threadIdx.x;
    if (i < NN) {
        int p = g_ptr[i] + g_bsum[blockIdx.x];
        g_ptr[i] = p;
        g_csr[p] = i;    // self loop at slot 0
        g_deg[i] = 1;    // scatter cursor
    }
}

__global__ void scatter_kernel(const void* __restrict__ ei) {
    int e = blockIdx.x * blockDim.x + threadIdx.x;
    if (e >= EE) return;
    int s, d;
    if (g_is64) {
        s = (int)((const long long*)ei)[e];
        d = (int)((const long long*)ei)[EE + e];
    } else {
        s = ((const int*)ei)[e];
        d = ((const int*)ei)[EE + e];
    }
    int pos = atomicAdd(&g_deg[d], 1);
    g_csr[g_ptr[d] + pos] = s;
}

// ---------------- big GEMM via mma.sync tf32 (3xTF32), 512 threads, 2 blocks/SM ----------------
// Block tile 128x128, K=128 in FOUR 32-wide chunks (shrinks smem to 72.7 KB -> 2 blocks/SM).
// 16 warps: wm=wid>>2 (32 rows), wn=wid&3 (32 cols = head wn).
#define XP2 36   // xs pitch (floats) for 32-wide K chunk
#define WP 136   // ws pitch (floats)
#define SP 132   // stage pitch (floats)

__global__ __launch_bounds__(512, 2)
void gemm_tc_kernel(const float* __restrict__ X, const float* __restrict__ W,
                    const float* __restrict__ att_s, const float* __restrict__ att_d,
                    float* __restrict__ H, float* __restrict__ asrc,
                    float* __restrict__ adst) {
    extern __shared__ char sh[];
    float* att_ss = (float*)sh;                        // 128 f
    float* att_ds = (float*)(sh + 512);                // 128 f
    uint32_t* xs_hi = (uint32_t*)(sh + 1024);          // [128][XP2]
    uint32_t* xs_lo = xs_hi + 128 * XP2;
    uint32_t* ws_hi = xs_lo + 128 * XP2;               // [32][WP]
    uint32_t* ws_lo = ws_hi + 32 * WP;
    float* stage = (float*)(sh + 1024);                // reused after mma

    int t = threadIdx.x;
    int lane = t & 31, wid = t >> 5;
    int g = lane >> 2, tig = lane & 3;
    int wm = wid >> 2, wn = wid & 3;
    int n0 = blockIdx.x * 128;

    if (t < 128) { att_ss[t] = att_s[t]; att_ds[t] = att_d[t]; }

    float acc[2][4][4];   // [mt 16-row][nt 8-col][frag]
    #pragma unroll
    for (int mt = 0; mt < 2; ++mt)
        #pragma unroll
        for (int nt = 0; nt < 4; ++nt)
            #pragma unroll
            for (int i = 0; i < 4; ++i) acc[mt][nt][i] = 0.f;

    for (int kc = 0; kc < 4; ++kc) {
        // load X[:, kc*32 .. +32) -> xs hi/lo  (128 rows x 8 float4)
        #pragma unroll 2
        for (int idx = t; idx < 128 * 8; idx += 512) {
            int r = idx >> 3, c4 = idx & 7;
            int n = n0 + r;
            float4 v = make_float4(0.f, 0.f, 0.f, 0.f);
            if (n < NN) v = ((const float4*)X)[(size_t)n * 32 + kc * 8 + c4];
            float e[4] = {v.x, v.y, v.z, v.w};
            #pragma unroll
            for (int j = 0; j < 4; ++j) {
                uint32_t hu = f2tf(e[j]);
                float lo = e[j] - __uint_as_float(hu);
                xs_hi[r * XP2 + c4 * 4 + j] = hu;
                xs_lo[r * XP2 + c4 * 4 + j] = f2tf(lo);
            }
        }
        // load W[kc*32 .. +32, :] -> ws hi/lo  (32 rows x 32 float4)
        #pragma unroll 2
        for (int idx = t; idx < 32 * 32; idx += 512) {
            int kr = idx >> 5, c4 = idx & 31;
            float4 v = ((const float4*)W)[(size_t)(kc * 32 + kr) * 32 + c4];
            float e[4] = {v.x, v.y, v.z, v.w};
            #pragma unroll
            for (int j = 0; j < 4; ++j) {
                uint32_t hu = f2tf(e[j]);
                float lo = e[j] - __uint_as_float(hu);
                ws_hi[kr * WP + c4 * 4 + j] = hu;
                ws_lo[kr * WP + c4 * 4 + j] = f2tf(lo);
            }
        }
        __syncthreads();

        const uint32_t* xa_h = xs_hi + (wm * 32 + g) * XP2 + tig;
        const uint32_t* xa_l = xs_lo + (wm * 32 + g) * XP2 + tig;
        const uint32_t* wb_h = ws_hi + tig * WP + wn * 32 + g;
        const uint32_t* wb_l = ws_lo + tig * WP + wn * 32 + g;

        #pragma unroll
        for (int ks = 0; ks < 4; ++ks) {
            uint32_t ah[2][4], al[2][4];
            #pragma unroll
            for (int mt = 0; mt < 2; ++mt) {
                int base = mt * 16 * XP2 + ks * 8;
                ah[mt][0] = xa_h[base];
                ah[mt][1] = xa_h[base + 8 * XP2];
                ah[mt][2] = xa_h[base + 4];
                ah[mt][3] = xa_h[base + 8 * XP2 + 4];
                al[mt][0] = xa_l[base];
                al[mt][1] = xa_l[base + 8 * XP2];
                al[mt][2] = xa_l[base + 4];
                al[mt][3] = xa_l[base + 8 * XP2 + 4];
            }
            #pragma unroll
            for (int nt = 0; nt < 4; ++nt) {
                int boff = ks * 8 * WP + nt * 8;
                uint32_t bh0 = wb_h[boff], bh1 = wb_h[boff + 4 * WP];
                uint32_t bl0 = wb_l[boff], bl1 = wb_l[boff + 4 * WP];
                #pragma unroll
                for (int mt = 0; mt < 2; ++mt) {
                    mma_tf32(acc[mt][nt], ah[mt], bh0, bh1);   // hi*hi
                    mma_tf32(acc[mt][nt], al[mt], bh0, bh1);   // lo*hi
                    mma_tf32(acc[mt][nt], ah[mt], bl0, bl1);   // hi*lo
                }
            }
        }
        __syncthreads();
    }

    // ---- epilogue: attention dots (warp covers exactly head wn) ----
    #pragma unroll
    for (int mt = 0; mt < 2; ++mt) {
        #pragma unroll
        for (int rh = 0; rh < 2; ++rh) {
            int n = n0 + wm * 32 + mt * 16 + g + rh * 8;
            float ps = 0.f, pd = 0.f;
            #pragma unroll
            for (int nt = 0; nt < 4; ++nt) {
                #pragma unroll
                for (int ci = 0; ci < 2; ++ci) {
                    int col = wn * 32 + nt * 8 + 2 * tig + ci;
                    float a = acc[mt][nt][rh * 2 + ci];
                    ps += a * att_ss[col];
                    pd += a * att_ds[col];
                }
            }
            #pragma unroll
            for (int off = 1; off <= 2; off <<= 1) {
                ps += __shfl_xor_sync(0xffffffffu, ps, off);
                pd += __shfl_xor_sync(0xffffffffu, pd, off);
            }
            if (tig == 0 && n < NN) {
                asrc[n * 4 + wn] = ps;
                adst[n * 4 + wn] = pd;
            }
        }
    }

    // ---- stage accs to smem, then interleaved H store ----
    #pragma unroll
    for (int mt = 0; mt < 2; ++mt) {
        int rbase = wm * 32 + mt * 16 + g;
        #pragma unroll
        for (int nt = 0; nt < 4; ++nt) {
            int col = wn * 32 + nt * 8 + 2 * tig;
            stage[rbase * SP + col] = acc[mt][nt][0];
            stage[rbase * SP + col + 1] = acc[mt][nt][1];
            stage[(rbase + 8) * SP + col] = acc[mt][nt][2];
            stage[(rbase + 8) * SP + col + 1] = acc[mt][nt][3];
        }
    }
    __syncthreads();
    #pragma unroll 2
    for (int idx = t; idx < 128 * 32; idx += 512) {
        int r = idx >> 5, fc = idx & 31;
        int n = n0 + r;
        if (n < NN) {
            const float* sr = stage + r * SP;
            ((float4*)H)[(size_t)n * 32 + fc] =
                make_float4(sr[fc], sr[32 + fc], sr[64 + fc], sr[96 + fc]);
        }
    }
}

// ---------------- small GEMM (M=32, heads=1, scalar f32x2) ----------------
__launch_bounds__(256)
__global__ void gemm32_kernel(const float* __restrict__ X, const float* __restrict__ W,
                              const float* __restrict__ att_s, const float* __restrict__ att_d,
                              float* __restrict__ H, float* __restrict__ asrc,
                              float* __restrict__ adst) {
    constexpr int CG = 8;
    constexpr int RPT = 2;
    constexpr int XS = 132;
    extern __shared__ float shf[];
    float* ws = shf;                 // 128*32
    float* xs = shf + 128 * 32;      // 64*XS

    int t = threadIdx.x;
    int n0 = blockIdx.x * 64;

    for (int i = t; i < 128 * 32 / 4; i += 256)
        ((float4*)ws)[i] = ((const float4*)W)[i];
    for (int i = t; i < 64 * 32; i += 256) {
        int r = i >> 5, c = i & 31;
        int n = n0 + r;
        float4 v = make_float4(0.f, 0.f, 0.f, 0.f);
        if (n < NN) v = ((const float4*)X)[(size_t)n * 32 + c];
        *((float4*)(xs + r * XS + c * 4)) = v;
    }
    __syncthreads();

    int cg = t % CG;
    int rg = t / CG;

    u64 acc2[RPT][2];
    #pragma unroll
    for (int r = 0; r < RPT; ++r) { acc2[r][0] = 0ull; acc2[r][1] = 0ull; }

    const ulonglong2* wsp = (const ulonglong2*)ws;
    #pragma unroll 8
    for (int k = 0; k < 128; ++k) {
        ulonglong2 wp = wsp[k * CG + cg];
        #pragma unroll
        for (int r = 0; r < RPT; ++r) {
            u64 xp = pack2(xs[(rg * RPT + r) * XS + k]);
            ffma2(acc2[r][0], xp, wp.x);
            ffma2(acc2[r][1], xp, wp.y);
        }
    }

    float4 as = ((const float4*)att_s)[cg];
    float4 ad = ((const float4*)att_d)[cg];
    #pragma unroll
    for (int r = 0; r < RPT; ++r) {
        float acc[4];
        unpack2(acc2[r][0], acc[0], acc[1]);
        unpack2(acc2[r][1], acc[2], acc[3]);
        int n = n0 + rg * RPT + r;
        float ps = acc[0] * as.x + acc[1] * as.y + acc[2] * as.z + acc[3] * as.w;
        float pd = acc[0] * ad.x + acc[1] * ad.y + acc[2] * ad.z + acc[3] * ad.w;
        #pragma unroll
        for (int off = 4; off >= 1; off >>= 1) {
            ps += __shfl_down_sync(0xffffffffu, ps, off, 8);
            pd += __shfl_down_sync(0xffffffffu, pd, off, 8);
        }
        if ((t & 7) == 0 && n < NN) {
            asrc[n] = ps;
            adst[n] = pd;
        }
        if (n < NN)
            ((float4*)H)[(size_t)n * CG + cg] = make_float4(acc[0], acc[1], acc[2], acc[3]);
    }
}

// ---------------- per-node ONLINE softmax + aggregation (single edge pass) ----------------
__device__ __forceinline__ float lrelu(float v) { return fmaxf(v, 0.2f * v); }

template <int HEADS, int ACT>   // ACT: 0 = ELU, 1 = sigmoid
__launch_bounds__(256)
__global__ void agg_kernel(const float* __restrict__ feat,
                           const float* __restrict__ asrc, const float* __restrict__ adst,
                           const float* __restrict__ bias, float* __restrict__ out) {
    __shared__ float4 s_w4[8][32];
    __shared__ int s_src[8][32];
    int wid = threadIdx.x >> 5;
    int lane = threadIdx.x & 31;
    int n = blockIdx.x * 8 + wid;
    if (n >= NN) return;
    int beg = g_ptr[n], end = g_ptr[n + 1];
    const float4* feat4 = (const float4*)feat;

    if (HEADS == 4) {
        float4 ad = ((const float4*)adst)[n];
        float m0 = -1e30f, m1 = -1e30f, m2 = -1e30f, m3 = -1e30f;
        float a0 = 0.f, a1 = 0.f, a2 = 0.f, a3 = 0.f;
        float s0 = 0.f, s1 = 0.f, s2 = 0.f, s3 = 0.f;
        for (int base = beg; base < end; base += 32) {
            int cnt = min(32, end - base);
            float l0 = -1e30f, l1 = -1e30f, l2 = -1e30f, l3 = -1e30f;
            int src = 0;
            if (lane < cnt) {
                src = g_csr[base + lane];
                float4 a = ((const float4*)asrc)[src];
                l0 = lrelu(a.x + ad.x);
                l1 = lrelu(a.y + ad.y);
                l2 = lrelu(a.z + ad.z);
                l3 = lrelu(a.w + ad.w);
            }
            float c0 = l0, c1 = l1, c2 = l2, c3 = l3;
            #pragma unroll
            for (int off = 16; off >= 1; off >>= 1) {
                c0 = fmaxf(c0, __shfl_xor_sync(0xffffffffu, c0, off));
                c1 = fmaxf(c1, __shfl_xor_sync(0xffffffffu, c1, off));
                c2 = fmaxf(c2, __shfl_xor_sync(0xffffffffu, c2, off));
                c3 = fmaxf(c3, __shfl_xor_sync(0xffffffffu, c3, off));
            }
            float nm0 = fmaxf(m0, c0), nm1 = fmaxf(m1, c1);
            float nm2 = fmaxf(m2, c2), nm3 = fmaxf(m3, c3);
            float f0 = __expf(m0 - nm0), f1 = __expf(m1 - nm1);
            float f2 = __expf(m2 - nm2), f3 = __expf(m3 - nm3);
            a0 *= f0; a1 *= f1; a2 *= f2; a3 *= f3;
            s0 *= f0; s1 *= f1; s2 *= f2; s3 *= f3;
            m0 = nm0; m1 = nm1; m2 = nm2; m3 = nm3;
            if (lane < cnt) {
                float4 wv;
                wv.x = __expf(l0 - m0);
                wv.y = __expf(l1 - m1);
                wv.z = __expf(l2 - m2);
                wv.w = __expf(l3 - m3);
                s_w4[wid][lane] = wv;
                s_src[wid][lane] = src;
            }
            __syncwarp();
            for (int i = 0; i < cnt; ++i) {
                float4 wv = s_w4[wid][i];
                int si = s_src[wid][i];
                float4 v = feat4[(size_t)si * 32 + lane];
                a0 += wv.x * v.x; a1 += wv.y * v.y; a2 += wv.z * v.z; a3 += wv.w * v.w;
                s0 += wv.x; s1 += wv.y; s2 += wv.z; s3 += wv.w;
            }
            __syncwarp();
        }
        float o0 = a0 / s0 + bias[lane];
        float o1 = a1 / s1 + bias[32 + lane];
        float o2 = a2 / s2 + bias[64 + lane];
        float o3 = a3 / s3 + bias[96 + lane];
        o0 = (o0 > 0.f) ? o0 : (__expf(o0) - 1.f);
        o1 = (o1 > 0.f) ? o1 : (__expf(o1) - 1.f);
        o2 = (o2 > 0.f) ? o2 : (__expf(o2) - 1.f);
        o3 = (o3 > 0.f) ? o3 : (__expf(o3) - 1.f);
        size_t b = (size_t)n * 128;
        out[b + lane] = o0;
        out[b + 32 + lane] = o1;
        out[b + 64 + lane] = o2;
        out[b + 96 + lane] = o3;
    } else {
        float* s_wf = (float*)&s_w4[wid][0];
        float ad = adst[n];
        float m = -1e30f, acc = 0.f, ssum = 0.f;
        for (int base = beg; base < end; base += 32) {
            int cnt = min(32, end - base);
            float l = -1e30f;
            int src = 0;
            if (lane < cnt) {
                src = g_csr[base + lane];
                l = lrelu(asrc[src] + ad);
            }
            float c = l;
            #pragma unroll
            for (int off = 16; off >= 1; off >>= 1)
                c = fmaxf(c, __shfl_xor_sync(0xffffffffu, c, off));
            float nm = fmaxf(m, c);
            float f = __expf(m - nm);
            acc *= f; ssum *= f;
            m = nm;
            if (lane < cnt) {
                s_wf[lane] = __expf(l - m);
                s_src[wid][lane] = src;
            }
            __syncwarp();
            for (int i = 0; i < cnt; ++i) {
                float wi = s_wf[i];
                int si = s_src[wid][i];
                acc += wi * feat[(size_t)si * 32 + lane];
                ssum += wi;
            }
            __syncwarp();
        }
        float o = acc / ssum + bias[lane];
        o = 1.f / (1.f + __expf(-o));
        out[(size_t)n * 32 + lane] = o;
    }
}

// ---------------- host launcher (single stream, capture-safe) ----------------
extern "C" void kernel_launch(void* const* d_in, const int* in_sizes, int n_in,
                              void* d_out, int out_size) {
    const float* x = (const float*)d_in[0];
    const void* ei = d_in[1];
    const float* W[4]  = {(const float*)d_in[2], (const float*)d_in[6],
                          (const float*)d_in[10], (const float*)d_in[14]};
    const float* As[4] = {(const float*)d_in[3], (const float*)d_in[7],
                          (const float*)d_in[11], (const float*)d_in[15]};
    const float* Ad[4] = {(const float*)d_in[4], (const float*)d_in[8],
                          (const float*)d_in[12], (const float*)d_in[16]};
    const float* B[4]  = {(const float*)d_in[5], (const float*)d_in[9],
                          (const float*)d_in[13], (const float*)d_in[17]};
    float* out = (float*)d_out;

    float *p_h0, *p_h1, *p_asrc, *p_adst;
    cudaGetSymbolAddress((void**)&p_h0, g_h0);
    cudaGetSymbolAddress((void**)&p_h1, g_h1);
    cudaGetSymbolAddress((void**)&p_asrc, g_asrc);
    cudaGetSymbolAddress((void**)&p_adst, g_adst);

    constexpr int SMEM_TC = 1024 + (2 * 128 * XP2 + 2 * 32 * WP) * 4;   // 72704 B
    constexpr int SMEM_SMALL = (128 * 32 + 64 * 132) * 4;               // 50176 B
    cudaFuncSetAttribute(gemm_tc_kernel,
                         cudaFuncAttributeMaxDynamicSharedMemorySize, SMEM_TC);
    cudaFuncSetAttribute(gemm32_kernel,
                         cudaFuncAttributeMaxDynamicSharedMemorySize, SMEM_SMALL);

    const int GTC = (NN + 127) / 128;  // 391
    const int GB = (NN + 63) / 64;     // 782
    const int AB = (NN + 7) / 8;       // 6250

    // CSR build, with layer-1 GEMM (CSR-independent) slotted at launch index 3
    // so the ncu capture lands on it.
    detect_kernel<<<1, 256>>>((const int*)ei);                             // 0
    init_deg_kernel<<<(NN + 255) / 256, 256>>>();                          // 1
    hist_kernel<<<(EE + 255) / 256, 256>>>(ei);                            // 2
    gemm_tc_kernel<<<GTC, 512, SMEM_TC>>>(x, W[0], As[0], Ad[0],           // 3 (profiled)
                                          p_h1, p_asrc, p_adst);
    scan_local_kernel<<<NBS, 1024>>>();                                    // 4
    scan_block_kernel<<<1, 32>>>();                                        // 5
    scan_add_kernel<<<NBS, 1024>>>();                                      // 6
    scatter_kernel<<<(EE + 255) / 256, 256>>>(ei);                         // 7

    // layer 1 aggregation
    agg_kernel<4, 0><<<AB, 256>>>(p_h1, p_asrc, p_adst, B[0], p_h0);
    // layer 2
    gemm_tc_kernel<<<GTC, 512, SMEM_TC>>>(p_h0, W[1], As[1], Ad[1], p_h1, p_asrc, p_adst);
    agg_kernel<4, 0><<<AB, 256>>>(p_h1, p_asrc, p_adst, B[1], p_h0);
    // layer 3
    gemm_tc_kernel<<<GTC, 512, SMEM_TC>>>(p_h0, W[2], As[2], Ad[2], p_h1, p_asrc, p_adst);
    agg_kernel<4, 0><<<AB, 256>>>(p_h1, p_asrc, p_adst, B[2], p_h0);
    // layer 4 (heads=1, 32 labels) -> sigmoid -> d_out
    gemm32_kernel<<<GB, 256, SMEM_SMALL>>>(p_h0, W[3], As[3], Ad[3], p_h1, p_asrc, p_adst);
    agg_kernel<1, 1><<<AB, 256>>>(p_h1, p_asrc, p_adst, B[3], out);
}